// round 1
// baseline (speedup 1.0000x reference)
#include <cuda_runtime.h>
#include <cuda_fp16.h>
#include <cstdint>

// ============================================================================
// CrossAttention: out = softmax((x Wq)(cond Wk)^T * s) (cond Wv) Wo + b
// B=2, SQ=SKV=2048, D_MODEL=1024, D_COND=768, H=16, DH=64
// Pipeline: fp32->fp16 converts -> 3 HMMA GEMMs (Q,K,V) -> flash attention
//           -> HMMA GEMM out-proj (+bias, fp32 out)
// ============================================================================

#define B_SZ    2
#define SQ      2048
#define SKV     2048
#define DMODEL  1024
#define DCOND   768
#define NHEADS  16
#define DHEAD   64
#define DATTN   1024
#define MROWS   (B_SZ * SQ)     // 4096

// --------------------------- scratch (device globals) -----------------------
__device__ __half g_xh [MROWS * DMODEL];
__device__ __half g_ch [MROWS * DCOND];
__device__ __half g_wq [DMODEL * DATTN];
__device__ __half g_wk [DCOND * DATTN];
__device__ __half g_wv [DCOND * DATTN];
__device__ __half g_wo [DATTN * DMODEL];
__device__ __half g_Q  [MROWS * DATTN];
__device__ __half g_K  [MROWS * DATTN];
__device__ __half g_V  [MROWS * DATTN];
__device__ __half g_AO [MROWS * DATTN];

// --------------------------- small helpers ----------------------------------
__device__ __forceinline__ uint32_t smem_u32(const void* p) {
    return (uint32_t)__cvta_generic_to_shared(p);
}

__device__ __forceinline__ void ldsm4(uint32_t* r, uint32_t addr) {
    asm volatile("ldmatrix.sync.aligned.m8n8.x4.shared.b16 {%0,%1,%2,%3}, [%4];"
                 : "=r"(r[0]), "=r"(r[1]), "=r"(r[2]), "=r"(r[3]) : "r"(addr));
}
__device__ __forceinline__ void ldsm4t(uint32_t* r, uint32_t addr) {
    asm volatile("ldmatrix.sync.aligned.m8n8.x4.trans.shared.b16 {%0,%1,%2,%3}, [%4];"
                 : "=r"(r[0]), "=r"(r[1]), "=r"(r[2]), "=r"(r[3]) : "r"(addr));
}
__device__ __forceinline__ void mma16816(float* c, const uint32_t* a, const uint32_t* b) {
    asm volatile(
        "mma.sync.aligned.m16n8k16.row.col.f32.f16.f16.f32 "
        "{%0,%1,%2,%3}, {%4,%5,%6,%7}, {%8,%9}, {%0,%1,%2,%3};"
        : "+f"(c[0]), "+f"(c[1]), "+f"(c[2]), "+f"(c[3])
        : "r"(a[0]), "r"(a[1]), "r"(a[2]), "r"(a[3]), "r"(b[0]), "r"(b[1]));
}
__device__ __forceinline__ uint32_t pack_h2(float a, float b) {
    __half2 h = __floats2half2_rn(a, b);
    return *reinterpret_cast<uint32_t*>(&h);
}

// --------------------------- fp32 -> fp16 convert ----------------------------
__global__ void f2h_kernel(const float* __restrict__ s, __half* __restrict__ d, int n) {
    int i = (blockIdx.x * blockDim.x + threadIdx.x) * 4;
    if (i < n) {
        float4 v = *reinterpret_cast<const float4*>(s + i);
        *reinterpret_cast<__half2*>(d + i)     = __floats2half2_rn(v.x, v.y);
        *reinterpret_cast<__half2*>(d + i + 2) = __floats2half2_rn(v.z, v.w);
    }
}

// --------------------------- HMMA GEMM ---------------------------------------
// C[M,N] = A[M,K] @ W[K,N]  (A,W fp16 row-major; C fp16 or fp32(+bias))
// Block 128x128x32, 256 threads, 8 warps as 2x4, warp tile 64x32.
template<int OUTF32, int HASBIAS>
__global__ __launch_bounds__(256)
void gemm_hmma(const __half* __restrict__ A, const __half* __restrict__ W,
               void* __restrict__ C, const float* __restrict__ bias,
               int M, int N, int K) {
    __shared__ __half As[128 * 40];   // ld=40 halves (80B) conflict-free
    __shared__ __half Bs[32 * 136];   // ld=136 halves (272B) conflict-free

    const int tid  = threadIdx.x;
    const int lane = tid & 31;
    const int wid  = tid >> 5;
    const int wm   = wid >> 2;   // 0..1
    const int wn   = wid & 3;    // 0..3
    const int brow = blockIdx.y * 128;
    const int bcol = blockIdx.x * 128;

    float acc[4][4][4];
    #pragma unroll
    for (int i = 0; i < 4; i++)
        #pragma unroll
        for (int j = 0; j < 4; j++)
            #pragma unroll
            for (int k = 0; k < 4; k++) acc[i][j][k] = 0.f;

    const uint32_t asm_b = smem_u32(As);
    const uint32_t bsm_b = smem_u32(Bs);
    // ldmatrix lane address components
    const int a_r = wm * 64 + (lane & 7) + (lane & 8);    // + mt*16
    const int a_c = (lane & 16) >> 1;                      // + ks*16
    const int b_k = (lane & 7) + (lane & 8);               // + ks*16
    const int b_n = wn * 32 + ((lane & 16) >> 1);          // + ntp*16

    for (int kt = 0; kt < K; kt += 32) {
        #pragma unroll
        for (int i = 0; i < 2; i++) {
            int r = (tid >> 2) + i * 64;
            int c = (tid & 3) * 8;
            *reinterpret_cast<uint4*>(&As[r * 40 + c]) =
                *reinterpret_cast<const uint4*>(&A[(size_t)(brow + r) * K + kt + c]);
        }
        #pragma unroll
        for (int i = 0; i < 2; i++) {
            int r = (tid >> 4) + i * 16;
            int c = (tid & 15) * 8;
            *reinterpret_cast<uint4*>(&Bs[r * 136 + c]) =
                *reinterpret_cast<const uint4*>(&W[(size_t)(kt + r) * N + bcol + c]);
        }
        __syncthreads();

        #pragma unroll
        for (int ks = 0; ks < 2; ks++) {
            uint32_t af[4][4], bf[4][2];
            #pragma unroll
            for (int mt = 0; mt < 4; mt++)
                ldsm4(af[mt], asm_b + (uint32_t)(((a_r + mt * 16) * 40 + ks * 16 + a_c) * 2));
            #pragma unroll
            for (int ntp = 0; ntp < 2; ntp++) {
                uint32_t r[4];
                ldsm4t(r, bsm_b + (uint32_t)(((ks * 16 + b_k) * 136 + b_n + ntp * 16) * 2));
                bf[ntp * 2][0] = r[0]; bf[ntp * 2][1] = r[1];
                bf[ntp * 2 + 1][0] = r[2]; bf[ntp * 2 + 1][1] = r[3];
            }
            #pragma unroll
            for (int mt = 0; mt < 4; mt++)
                #pragma unroll
                for (int nt = 0; nt < 4; nt++)
                    mma16816(acc[mt][nt], af[mt], bf[nt]);
        }
        __syncthreads();
    }

    const int er = brow + wm * 64 + (lane >> 2);
    const int ec = bcol + wn * 32 + 2 * (lane & 3);
    #pragma unroll
    for (int mt = 0; mt < 4; mt++) {
        #pragma unroll
        for (int nt = 0; nt < 4; nt++) {
            int r0 = er + mt * 16;
            int c  = ec + nt * 8;
            if (OUTF32) {
                float* O = (float*)C;
                float b0 = HASBIAS ? bias[c]     : 0.f;
                float b1 = HASBIAS ? bias[c + 1] : 0.f;
                O[(size_t)r0 * N + c]           = acc[mt][nt][0] + b0;
                O[(size_t)r0 * N + c + 1]       = acc[mt][nt][1] + b1;
                O[(size_t)(r0 + 8) * N + c]     = acc[mt][nt][2] + b0;
                O[(size_t)(r0 + 8) * N + c + 1] = acc[mt][nt][3] + b1;
            } else {
                __half* O = (__half*)C;
                *reinterpret_cast<__half2*>(&O[(size_t)r0 * N + c]) =
                    __floats2half2_rn(acc[mt][nt][0], acc[mt][nt][1]);
                *reinterpret_cast<__half2*>(&O[(size_t)(r0 + 8) * N + c]) =
                    __floats2half2_rn(acc[mt][nt][2], acc[mt][nt][3]);
            }
        }
    }
}

// --------------------------- flash attention ---------------------------------
// grid (SQ/64, H, B), 128 threads (4 warps). Warp w handles 16 q rows.
__global__ __launch_bounds__(128)
void flash_attn(const __half* __restrict__ Qg, const __half* __restrict__ Kg,
                const __half* __restrict__ Vg, __half* __restrict__ Og) {
    __shared__ __half Qs[64 * 72], Ks[64 * 72], Vs[64 * 72];  // ld=72 (144B) conflict-free

    const int tid  = threadIdx.x;
    const int lane = tid & 31;
    const int warp = tid >> 5;
    const int b = blockIdx.z, h = blockIdx.y;
    const int q0 = blockIdx.x * 64;
    const float scale = 0.125f;   // DHEAD^-0.5

    // load Q tile [64 x 64] at column offset h*64
    for (int i = tid; i < 512; i += 128) {
        int r = i >> 3, c = (i & 7) * 8;
        *reinterpret_cast<uint4*>(&Qs[r * 72 + c]) =
            *reinterpret_cast<const uint4*>(&Qg[(size_t)(b * SQ + q0 + r) * DATTN + h * DHEAD + c]);
    }
    __syncthreads();

    const uint32_t qsm = smem_u32(Qs), ksm = smem_u32(Ks), vsm = smem_u32(Vs);
    const int a_r  = warp * 16 + (lane & 7) + (lane & 8);
    const int a_c  = (lane & 16) >> 1;
    const int kb_n = (lane & 7) + ((lane & 16) >> 1);  // + ntp*16  (non-trans: rows = kv)
    const int kb_c = (lane & 8);                        // + ks*16
    const int vb_k = (lane & 7) + (lane & 8);           // + j*16    (trans: rows = kv)
    const int vb_d = (lane & 16) >> 1;                  // + p*16

    // preload Q A-fragments (reused every kv iteration)
    uint32_t qf[4][4];
    #pragma unroll
    for (int ks = 0; ks < 4; ks++)
        ldsm4(qf[ks], qsm + (uint32_t)((a_r * 72 + ks * 16 + a_c) * 2));

    float of[8][4];
    #pragma unroll
    for (int i = 0; i < 8; i++) { of[i][0]=of[i][1]=of[i][2]=of[i][3]=0.f; }
    float m0 = -1e30f, m1 = -1e30f, l0 = 0.f, l1 = 0.f;

    for (int kv0 = 0; kv0 < SKV; kv0 += 64) {
        __syncthreads();
        for (int i = tid; i < 512; i += 128) {
            int r = i >> 3, c = (i & 7) * 8;
            size_t g = (size_t)(b * SKV + kv0 + r) * DATTN + h * DHEAD + c;
            *reinterpret_cast<uint4*>(&Ks[r * 72 + c]) = *reinterpret_cast<const uint4*>(&Kg[g]);
            *reinterpret_cast<uint4*>(&Vs[r * 72 + c]) = *reinterpret_cast<const uint4*>(&Vg[g]);
        }
        __syncthreads();

        // S = Q K^T  (16 x 64 per warp)
        float sf[8][4];
        #pragma unroll
        for (int i = 0; i < 8; i++) { sf[i][0]=sf[i][1]=sf[i][2]=sf[i][3]=0.f; }
        #pragma unroll
        for (int ks = 0; ks < 4; ks++) {
            uint32_t bf[8][2];
            #pragma unroll
            for (int ntp = 0; ntp < 4; ntp++) {
                uint32_t r[4];
                ldsm4(r, ksm + (uint32_t)(((ntp * 16 + kb_n) * 72 + ks * 16 + kb_c) * 2));
                bf[ntp * 2][0] = r[0]; bf[ntp * 2][1] = r[1];
                bf[ntp * 2 + 1][0] = r[2]; bf[ntp * 2 + 1][1] = r[3];
            }
            #pragma unroll
            for (int nt = 0; nt < 8; nt++) mma16816(sf[nt], qf[ks], bf[nt]);
        }

        // online softmax (row r = lane>>2 -> [0],[1]; row r+8 -> [2],[3])
        float mx0 = -1e30f, mx1 = -1e30f;
        #pragma unroll
        for (int nt = 0; nt < 8; nt++) {
            sf[nt][0] *= scale; sf[nt][1] *= scale; sf[nt][2] *= scale; sf[nt][3] *= scale;
            mx0 = fmaxf(mx0, fmaxf(sf[nt][0], sf[nt][1]));
            mx1 = fmaxf(mx1, fmaxf(sf[nt][2], sf[nt][3]));
        }
        #pragma unroll
        for (int off = 1; off < 4; off <<= 1) {
            mx0 = fmaxf(mx0, __shfl_xor_sync(0xffffffffu, mx0, off));
            mx1 = fmaxf(mx1, __shfl_xor_sync(0xffffffffu, mx1, off));
        }
        float mn0 = fmaxf(m0, mx0), mn1 = fmaxf(m1, mx1);
        float al0 = __expf(m0 - mn0), al1 = __expf(m1 - mn1);
        float rs0 = 0.f, rs1 = 0.f;
        #pragma unroll
        for (int nt = 0; nt < 8; nt++) {
            sf[nt][0] = __expf(sf[nt][0] - mn0);
            sf[nt][1] = __expf(sf[nt][1] - mn0);
            sf[nt][2] = __expf(sf[nt][2] - mn1);
            sf[nt][3] = __expf(sf[nt][3] - mn1);
            rs0 += sf[nt][0] + sf[nt][1];
            rs1 += sf[nt][2] + sf[nt][3];
        }
        #pragma unroll
        for (int off = 1; off < 4; off <<= 1) {
            rs0 += __shfl_xor_sync(0xffffffffu, rs0, off);
            rs1 += __shfl_xor_sync(0xffffffffu, rs1, off);
        }
        l0 = l0 * al0 + rs0; m0 = mn0;
        l1 = l1 * al1 + rs1; m1 = mn1;
        #pragma unroll
        for (int dt = 0; dt < 8; dt++) {
            of[dt][0] *= al0; of[dt][1] *= al0; of[dt][2] *= al1; of[dt][3] *= al1;
        }

        // O += P V  : P A-frags repacked from S C-frags
        #pragma unroll
        for (int j = 0; j < 4; j++) {
            uint32_t pa[4];
            pa[0] = pack_h2(sf[2 * j][0],     sf[2 * j][1]);
            pa[1] = pack_h2(sf[2 * j][2],     sf[2 * j][3]);
            pa[2] = pack_h2(sf[2 * j + 1][0], sf[2 * j + 1][1]);
            pa[3] = pack_h2(sf[2 * j + 1][2], sf[2 * j + 1][3]);
            uint32_t bf[8][2];
            #pragma unroll
            for (int p = 0; p < 4; p++) {
                uint32_t r[4];
                ldsm4t(r, vsm + (uint32_t)(((j * 16 + vb_k) * 72 + p * 16 + vb_d) * 2));
                bf[p * 2][0] = r[0]; bf[p * 2][1] = r[1];
                bf[p * 2 + 1][0] = r[2]; bf[p * 2 + 1][1] = r[3];
            }
            #pragma unroll
            for (int dt = 0; dt < 8; dt++) mma16816(of[dt], pa, bf[dt]);
        }
    }

    // normalize + store fp16 to attn-out buffer
    float inv0 = 1.f / l0, inv1 = 1.f / l1;
    const int r0 = b * SQ + q0 + warp * 16 + (lane >> 2);
    const int cb = h * DHEAD + 2 * (lane & 3);
    #pragma unroll
    for (int dt = 0; dt < 8; dt++) {
        int c = cb + dt * 8;
        *reinterpret_cast<__half2*>(&Og[(size_t)r0 * DATTN + c]) =
            __floats2half2_rn(of[dt][0] * inv0, of[dt][1] * inv0);
        *reinterpret_cast<__half2*>(&Og[(size_t)(r0 + 8) * DATTN + c]) =
            __floats2half2_rn(of[dt][2] * inv1, of[dt][3] * inv1);
    }
}

// --------------------------- launch ------------------------------------------
extern "C" void kernel_launch(void* const* d_in, const int* in_sizes, int n_in,
                              void* d_out, int out_size) {
    (void)in_sizes; (void)n_in; (void)out_size;
    const float* x    = (const float*)d_in[0];
    const float* cond = (const float*)d_in[1];
    const float* wq   = (const float*)d_in[2];
    const float* wk   = (const float*)d_in[3];
    const float* wv   = (const float*)d_in[4];
    const float* wo   = (const float*)d_in[5];
    const float* bo   = (const float*)d_in[6];

    __half *xh, *ch, *wqh, *wkh, *wvh, *woh, *Qb, *Kb, *Vb, *AOb;
    cudaGetSymbolAddress((void**)&xh,  g_xh);
    cudaGetSymbolAddress((void**)&ch,  g_ch);
    cudaGetSymbolAddress((void**)&wqh, g_wq);
    cudaGetSymbolAddress((void**)&wkh, g_wk);
    cudaGetSymbolAddress((void**)&wvh, g_wv);
    cudaGetSymbolAddress((void**)&woh, g_wo);
    cudaGetSymbolAddress((void**)&Qb,  g_Q);
    cudaGetSymbolAddress((void**)&Kb,  g_K);
    cudaGetSymbolAddress((void**)&Vb,  g_V);
    cudaGetSymbolAddress((void**)&AOb, g_AO);

    auto cvt = [&](const float* s, __half* d, int n) {
        f2h_kernel<<<(n / 4 + 255) / 256, 256>>>(s, d, n);
    };
    cvt(x,    xh,  MROWS * DMODEL);
    cvt(cond, ch,  MROWS * DCOND);
    cvt(wq,   wqh, DMODEL * DATTN);
    cvt(wk,   wkh, DCOND * DATTN);
    cvt(wv,   wvh, DCOND * DATTN);
    cvt(wo,   woh, DATTN * DMODEL);

    dim3 gproj(DATTN / 128, MROWS / 128);   // (8, 32)
    gemm_hmma<0, 0><<<gproj, 256>>>(xh, wqh, Qb, nullptr, MROWS, DATTN, DMODEL);
    gemm_hmma<0, 0><<<gproj, 256>>>(ch, wkh, Kb, nullptr, MROWS, DATTN, DCOND);
    gemm_hmma<0, 0><<<gproj, 256>>>(ch, wvh, Vb, nullptr, MROWS, DATTN, DCOND);

    flash_attn<<<dim3(SQ / 64, NHEADS, B_SZ), 128>>>(Qb, Kb, Vb, AOb);

    dim3 gout(DMODEL / 128, MROWS / 128);
    gemm_hmma<1, 1><<<gout, 256>>>(AOb, woh, d_out, bo, MROWS, DMODEL, DATTN);
}

// round 3
// speedup vs baseline: 1.1625x; 1.1625x over previous
#include <cuda_runtime.h>
#include <cuda_fp16.h>
#include <cstdint>

// ============================================================================
// CrossAttention: out = softmax((x Wq)(cond Wk)^T * s) (cond Wv) Wo + b
// B=2, SQ=SKV=2048, D_MODEL=1024, D_COND=768, H=16, DH=64
// R3: R2 pipeline (cp.async double-buffered GEMM + flash-attn, BM=128,
//     log2-domain softmax) with attention smem overlaid into 36.8KB static
//     (no dynamic smem, no cudaFuncSetAttribute).
// ============================================================================

#define B_SZ    2
#define SQ      2048
#define SKV     2048
#define DMODEL  1024
#define DCOND   768
#define NHEADS  16
#define DHEAD   64
#define DATTN   1024
#define MROWS   (B_SZ * SQ)     // 4096

// --------------------------- scratch (device globals) -----------------------
__device__ __half g_xh [MROWS * DMODEL];
__device__ __half g_ch [MROWS * DCOND];
__device__ __half g_wq [DMODEL * DATTN];
__device__ __half g_wk [DCOND * DATTN];
__device__ __half g_wv [DCOND * DATTN];
__device__ __half g_wo [DATTN * DMODEL];
__device__ __half g_Q  [MROWS * DATTN];
__device__ __half g_K  [MROWS * DATTN];
__device__ __half g_V  [MROWS * DATTN];
__device__ __half g_AO [MROWS * DATTN];

// --------------------------- small helpers ----------------------------------
__device__ __forceinline__ uint32_t smem_u32(const void* p) {
    return (uint32_t)__cvta_generic_to_shared(p);
}
__device__ __forceinline__ void cp16(uint32_t dst, const void* src) {
    asm volatile("cp.async.cg.shared.global [%0], [%1], 16;" :: "r"(dst), "l"(src));
}
__device__ __forceinline__ void cp_commit() {
    asm volatile("cp.async.commit_group;");
}
template<int N> __device__ __forceinline__ void cp_wait() {
    asm volatile("cp.async.wait_group %0;" :: "n"(N));
}
__device__ __forceinline__ void ldsm4(uint32_t* r, uint32_t addr) {
    asm volatile("ldmatrix.sync.aligned.m8n8.x4.shared.b16 {%0,%1,%2,%3}, [%4];"
                 : "=r"(r[0]), "=r"(r[1]), "=r"(r[2]), "=r"(r[3]) : "r"(addr));
}
__device__ __forceinline__ void ldsm4t(uint32_t* r, uint32_t addr) {
    asm volatile("ldmatrix.sync.aligned.m8n8.x4.trans.shared.b16 {%0,%1,%2,%3}, [%4];"
                 : "=r"(r[0]), "=r"(r[1]), "=r"(r[2]), "=r"(r[3]) : "r"(addr));
}
__device__ __forceinline__ void mma16816(float* c, const uint32_t* a, const uint32_t* b) {
    asm volatile(
        "mma.sync.aligned.m16n8k16.row.col.f32.f16.f16.f32 "
        "{%0,%1,%2,%3}, {%4,%5,%6,%7}, {%8,%9}, {%0,%1,%2,%3};"
        : "+f"(c[0]), "+f"(c[1]), "+f"(c[2]), "+f"(c[3])
        : "r"(a[0]), "r"(a[1]), "r"(a[2]), "r"(a[3]), "r"(b[0]), "r"(b[1]));
}
__device__ __forceinline__ uint32_t pack_h2(float a, float b) {
    __half2 h = __floats2half2_rn(a, b);
    return *reinterpret_cast<uint32_t*>(&h);
}
__device__ __forceinline__ float ex2(float x) {
    float r; asm("ex2.approx.ftz.f32 %0, %1;" : "=f"(r) : "f"(x)); return r;
}

// --------------------------- fp32 -> fp16 convert (optional scale) ----------
__global__ void f2h_kernel(const float* __restrict__ s, __half* __restrict__ d,
                           int n, float scale) {
    int i = (blockIdx.x * blockDim.x + threadIdx.x) * 4;
    if (i < n) {
        float4 v = *reinterpret_cast<const float4*>(s + i);
        *reinterpret_cast<__half2*>(d + i)     = __floats2half2_rn(v.x * scale, v.y * scale);
        *reinterpret_cast<__half2*>(d + i + 2) = __floats2half2_rn(v.z * scale, v.w * scale);
    }
}

// --------------------------- HMMA GEMM (2-stage cp.async pipeline) ----------
// C[M,N] = A[M,K] @ W[K,N]. Block 128x128x32, 256 threads, 8 warps (2x4).
// KVMODE: blockIdx.z selects between two weight/output pairs (K/V projection).
template<int OUTF32, int HASBIAS, int KVMODE>
__global__ __launch_bounds__(256)
void gemm_hmma(const __half* __restrict__ A,
               const __half* __restrict__ W0, const __half* __restrict__ W1,
               void* __restrict__ C0, void* __restrict__ C1,
               const float* __restrict__ bias, int M, int N, int K) {
    __shared__ __half As[2][128 * 40];   // ld=40 halves conflict-free
    __shared__ __half Bs[2][32 * 136];   // ld=136 halves conflict-free

    const __half* W = (KVMODE && blockIdx.z) ? W1 : W0;
    void* C         = (KVMODE && blockIdx.z) ? C1 : C0;

    const int tid  = threadIdx.x;
    const int lane = tid & 31;
    const int wid  = tid >> 5;
    const int wm   = wid >> 2;
    const int wn   = wid & 3;
    const int brow = blockIdx.y * 128;
    const int bcol = blockIdx.x * 128;

    const int ar = tid >> 2, ac = (tid & 3) * 8;
    const int br = tid >> 4, bc = (tid & 15) * 8;

    auto loadTile = [&](int kt, int buf) {
        #pragma unroll
        for (int i = 0; i < 2; i++) {
            int r = ar + i * 64;
            cp16(smem_u32(&As[buf][r * 40 + ac]),
                 &A[(size_t)(brow + r) * K + kt + ac]);
        }
        #pragma unroll
        for (int i = 0; i < 2; i++) {
            int r = br + i * 16;
            cp16(smem_u32(&Bs[buf][r * 136 + bc]),
                 &W[(size_t)(kt + r) * N + bcol + bc]);
        }
    };

    float acc[4][4][4];
    #pragma unroll
    for (int i = 0; i < 4; i++)
        #pragma unroll
        for (int j = 0; j < 4; j++)
            #pragma unroll
            for (int k = 0; k < 4; k++) acc[i][j][k] = 0.f;

    const int a_r = wm * 64 + (lane & 7) + (lane & 8);
    const int a_c = (lane & 16) >> 1;
    const int b_k = (lane & 7) + (lane & 8);
    const int b_n = wn * 32 + ((lane & 16) >> 1);

    const int T = K / 32;
    loadTile(0, 0);
    cp_commit();

    for (int t = 0; t < T; t++) {
        if (t + 1 < T) { loadTile((t + 1) * 32, (t + 1) & 1); cp_commit(); cp_wait<1>(); }
        else           { cp_wait<0>(); }
        __syncthreads();

        const uint32_t asm_b = smem_u32(As[t & 1]);
        const uint32_t bsm_b = smem_u32(Bs[t & 1]);
        #pragma unroll
        for (int ks = 0; ks < 2; ks++) {
            uint32_t af[4][4], bf[4][2];
            #pragma unroll
            for (int mt = 0; mt < 4; mt++)
                ldsm4(af[mt], asm_b + (uint32_t)(((a_r + mt * 16) * 40 + ks * 16 + a_c) * 2));
            #pragma unroll
            for (int ntp = 0; ntp < 2; ntp++) {
                uint32_t r[4];
                ldsm4t(r, bsm_b + (uint32_t)(((ks * 16 + b_k) * 136 + b_n + ntp * 16) * 2));
                bf[ntp * 2][0] = r[0]; bf[ntp * 2][1] = r[1];
                bf[ntp * 2 + 1][0] = r[2]; bf[ntp * 2 + 1][1] = r[3];
            }
            #pragma unroll
            for (int mt = 0; mt < 4; mt++)
                #pragma unroll
                for (int nt = 0; nt < 4; nt++)
                    mma16816(acc[mt][nt], af[mt], bf[nt]);
        }
        __syncthreads();
    }

    const int er = brow + wm * 64 + (lane >> 2);
    const int ec = bcol + wn * 32 + 2 * (lane & 3);
    #pragma unroll
    for (int mt = 0; mt < 4; mt++) {
        #pragma unroll
        for (int nt = 0; nt < 4; nt++) {
            int r0 = er + mt * 16;
            int c  = ec + nt * 8;
            if (OUTF32) {
                float* O = (float*)C;
                float b0 = HASBIAS ? bias[c]     : 0.f;
                float b1 = HASBIAS ? bias[c + 1] : 0.f;
                O[(size_t)r0 * N + c]           = acc[mt][nt][0] + b0;
                O[(size_t)r0 * N + c + 1]       = acc[mt][nt][1] + b1;
                O[(size_t)(r0 + 8) * N + c]     = acc[mt][nt][2] + b0;
                O[(size_t)(r0 + 8) * N + c + 1] = acc[mt][nt][3] + b1;
            } else {
                __half* O = (__half*)C;
                *reinterpret_cast<__half2*>(&O[(size_t)r0 * N + c]) =
                    __floats2half2_rn(acc[mt][nt][0], acc[mt][nt][1]);
                *reinterpret_cast<__half2*>(&O[(size_t)(r0 + 8) * N + c]) =
                    __floats2half2_rn(acc[mt][nt][2], acc[mt][nt][3]);
            }
        }
    }
}

// --------------------------- flash attention ---------------------------------
// grid (SQ/128, H, B), 256 threads (8 warps), warp w -> 16 q rows.
// KV tile 64, double-buffered via cp.async. Q logits pre-scaled by
// 0.125*log2(e) at projection time -> softmax via ex2.
// Static smem 36864B: Q tile (128x72 = 9216 halves) is staged into the same
// region as the KV double buffer, fragments extracted, then KV pipeline runs.
__global__ __launch_bounds__(256)
void flash_attn(const __half* __restrict__ Qg, const __half* __restrict__ Kg,
                const __half* __restrict__ Vg, __half* __restrict__ Og) {
    __shared__ __half sm[2 * 9216];   // 36864 B

    const int tid  = threadIdx.x;
    const int lane = tid & 31;
    const int warp = tid >> 5;
    const int b = blockIdx.z, h = blockIdx.y;
    const int q0 = blockIdx.x * 128;

    auto Kbuf = [&](int p) { return sm + p * 9216; };
    auto Vbuf = [&](int p) { return sm + p * 9216 + 4608; };

    auto loadKV = [&](int kv0, int p) {
        __half* kd = Kbuf(p);
        __half* vd = Vbuf(p);
        #pragma unroll
        for (int i = tid; i < 1024; i += 256) {
            int mat = i >> 9, idx = i & 511;
            int r = idx >> 3, c = (idx & 7) * 8;
            const __half* src = (mat ? Vg : Kg) +
                (size_t)(b * SKV + kv0 + r) * DATTN + h * DHEAD + c;
            __half* dst = (mat ? vd : kd) + r * 72 + c;
            cp16(smem_u32(dst), src);
        }
    };

    // ---- stage Q into sm[0..9216), extract fragments, then free the space
    for (int i = tid; i < 1024; i += 256) {
        int r = i >> 3, c = (i & 7) * 8;
        *reinterpret_cast<uint4*>(&sm[r * 72 + c]) =
            *reinterpret_cast<const uint4*>(
                &Qg[(size_t)(b * SQ + q0 + r) * DATTN + h * DHEAD + c]);
    }
    __syncthreads();

    const int a_r  = warp * 16 + (lane & 7) + (lane & 8);
    const int a_c  = (lane & 16) >> 1;
    const int kb_n = (lane & 7) + ((lane & 16) >> 1);
    const int kb_c = (lane & 8);
    const int vb_k = (lane & 7) + (lane & 8);
    const int vb_d = (lane & 16) >> 1;

    uint32_t qf[4][4];
    const uint32_t qsm = smem_u32(sm);
    #pragma unroll
    for (int ks = 0; ks < 4; ks++)
        ldsm4(qf[ks], qsm + (uint32_t)((a_r * 72 + ks * 16 + a_c) * 2));
    __syncthreads();   // all warps done reading Q before KV overwrites

    loadKV(0, 0);
    cp_commit();

    float of[8][4];
    #pragma unroll
    for (int i = 0; i < 8; i++) { of[i][0]=of[i][1]=of[i][2]=of[i][3]=0.f; }
    float m0 = -1e30f, m1 = -1e30f, l0 = 0.f, l1 = 0.f;

    const int NIT = SKV / 64;
    for (int it = 0; it < NIT; it++) {
        if (it + 1 < NIT) { loadKV((it + 1) * 64, (it + 1) & 1); cp_commit(); cp_wait<1>(); }
        else              { cp_wait<0>(); }
        __syncthreads();

        const uint32_t ksm = smem_u32(Kbuf(it & 1));
        const uint32_t vsm = smem_u32(Vbuf(it & 1));

        // S = Q K^T (already in log2 units, pre-scaled)
        float sf[8][4];
        #pragma unroll
        for (int i = 0; i < 8; i++) { sf[i][0]=sf[i][1]=sf[i][2]=sf[i][3]=0.f; }
        #pragma unroll
        for (int ks = 0; ks < 4; ks++) {
            uint32_t bf[8][2];
            #pragma unroll
            for (int ntp = 0; ntp < 4; ntp++) {
                uint32_t r[4];
                ldsm4(r, ksm + (uint32_t)(((ntp * 16 + kb_n) * 72 + ks * 16 + kb_c) * 2));
                bf[ntp * 2][0] = r[0]; bf[ntp * 2][1] = r[1];
                bf[ntp * 2 + 1][0] = r[2]; bf[ntp * 2 + 1][1] = r[3];
            }
            #pragma unroll
            for (int nt = 0; nt < 8; nt++) mma16816(sf[nt], qf[ks], bf[nt]);
        }

        // online softmax in log2 domain
        float mx0 = -1e30f, mx1 = -1e30f;
        #pragma unroll
        for (int nt = 0; nt < 8; nt++) {
            mx0 = fmaxf(mx0, fmaxf(sf[nt][0], sf[nt][1]));
            mx1 = fmaxf(mx1, fmaxf(sf[nt][2], sf[nt][3]));
        }
        #pragma unroll
        for (int off = 1; off < 4; off <<= 1) {
            mx0 = fmaxf(mx0, __shfl_xor_sync(0xffffffffu, mx0, off));
            mx1 = fmaxf(mx1, __shfl_xor_sync(0xffffffffu, mx1, off));
        }
        float mn0 = fmaxf(m0, mx0), mn1 = fmaxf(m1, mx1);
        float al0 = ex2(m0 - mn0), al1 = ex2(m1 - mn1);
        float rs0 = 0.f, rs1 = 0.f;
        #pragma unroll
        for (int nt = 0; nt < 8; nt++) {
            sf[nt][0] = ex2(sf[nt][0] - mn0);
            sf[nt][1] = ex2(sf[nt][1] - mn0);
            sf[nt][2] = ex2(sf[nt][2] - mn1);
            sf[nt][3] = ex2(sf[nt][3] - mn1);
            rs0 += sf[nt][0] + sf[nt][1];
            rs1 += sf[nt][2] + sf[nt][3];
        }
        #pragma unroll
        for (int off = 1; off < 4; off <<= 1) {
            rs0 += __shfl_xor_sync(0xffffffffu, rs0, off);
            rs1 += __shfl_xor_sync(0xffffffffu, rs1, off);
        }
        l0 = l0 * al0 + rs0; m0 = mn0;
        l1 = l1 * al1 + rs1; m1 = mn1;
        #pragma unroll
        for (int dt = 0; dt < 8; dt++) {
            of[dt][0] *= al0; of[dt][1] *= al0; of[dt][2] *= al1; of[dt][3] *= al1;
        }

        // O += P V
        #pragma unroll
        for (int j = 0; j < 4; j++) {
            uint32_t pa[4];
            pa[0] = pack_h2(sf[2 * j][0],     sf[2 * j][1]);
            pa[1] = pack_h2(sf[2 * j][2],     sf[2 * j][3]);
            pa[2] = pack_h2(sf[2 * j + 1][0], sf[2 * j + 1][1]);
            pa[3] = pack_h2(sf[2 * j + 1][2], sf[2 * j + 1][3]);
            uint32_t bf[8][2];
            #pragma unroll
            for (int p = 0; p < 4; p++) {
                uint32_t r[4];
                ldsm4t(r, vsm + (uint32_t)(((j * 16 + vb_k) * 72 + p * 16 + vb_d) * 2));
                bf[p * 2][0] = r[0]; bf[p * 2][1] = r[1];
                bf[p * 2 + 1][0] = r[2]; bf[p * 2 + 1][1] = r[3];
            }
            #pragma unroll
            for (int dt = 0; dt < 8; dt++) mma16816(of[dt], pa, bf[dt]);
        }
        __syncthreads();
    }

    float inv0 = 1.f / l0, inv1 = 1.f / l1;
    const int r0 = b * SQ + q0 + warp * 16 + (lane >> 2);
    const int cb = h * DHEAD + 2 * (lane & 3);
    #pragma unroll
    for (int dt = 0; dt < 8; dt++) {
        int c = cb + dt * 8;
        *reinterpret_cast<__half2*>(&Og[(size_t)r0 * DATTN + c]) =
            __floats2half2_rn(of[dt][0] * inv0, of[dt][1] * inv0);
        *reinterpret_cast<__half2*>(&Og[(size_t)(r0 + 8) * DATTN + c]) =
            __floats2half2_rn(of[dt][2] * inv1, of[dt][3] * inv1);
    }
}

// --------------------------- launch ------------------------------------------
extern "C" void kernel_launch(void* const* d_in, const int* in_sizes, int n_in,
                              void* d_out, int out_size) {
    (void)in_sizes; (void)n_in; (void)out_size;
    const float* x    = (const float*)d_in[0];
    const float* cond = (const float*)d_in[1];
    const float* wq   = (const float*)d_in[2];
    const float* wk   = (const float*)d_in[3];
    const float* wv   = (const float*)d_in[4];
    const float* wo   = (const float*)d_in[5];
    const float* bo   = (const float*)d_in[6];

    __half *xh, *ch, *wqh, *wkh, *wvh, *woh, *Qb, *Kb, *Vb, *AOb;
    cudaGetSymbolAddress((void**)&xh,  g_xh);
    cudaGetSymbolAddress((void**)&ch,  g_ch);
    cudaGetSymbolAddress((void**)&wqh, g_wq);
    cudaGetSymbolAddress((void**)&wkh, g_wk);
    cudaGetSymbolAddress((void**)&wvh, g_wv);
    cudaGetSymbolAddress((void**)&woh, g_wo);
    cudaGetSymbolAddress((void**)&Qb,  g_Q);
    cudaGetSymbolAddress((void**)&Kb,  g_K);
    cudaGetSymbolAddress((void**)&Vb,  g_V);
    cudaGetSymbolAddress((void**)&AOb, g_AO);

    const float QSCALE = 0.125f * 1.44269504088896f;  // d^-0.5 * log2(e)
    auto cvt = [&](const float* s, __half* d, int n, float sc) {
        f2h_kernel<<<(n / 4 + 255) / 256, 256>>>(s, d, n, sc);
    };
    cvt(x,    xh,  MROWS * DMODEL, 1.f);
    cvt(cond, ch,  MROWS * DCOND,  1.f);
    cvt(wq,   wqh, DMODEL * DATTN, QSCALE);
    cvt(wk,   wkh, DCOND * DATTN,  1.f);
    cvt(wv,   wvh, DCOND * DATTN,  1.f);
    cvt(wo,   woh, DATTN * DMODEL, 1.f);

    dim3 gq(DATTN / 128, MROWS / 128, 1);     // (8, 32)
    gemm_hmma<0, 0, 0><<<gq, 256>>>(xh, wqh, nullptr, Qb, nullptr, nullptr,
                                    MROWS, DATTN, DMODEL);
    dim3 gkv(DATTN / 128, MROWS / 128, 2);    // (8, 32, 2)
    gemm_hmma<0, 0, 1><<<gkv, 256>>>(ch, wkh, wvh, Kb, Vb, nullptr,
                                     MROWS, DATTN, DCOND);

    flash_attn<<<dim3(SQ / 128, NHEADS, B_SZ), 256>>>(Qb, Kb, Vb, AOb);

    dim3 gout(DMODEL / 128, MROWS / 128, 1);
    gemm_hmma<1, 1, 0><<<gout, 256>>>(AOb, woh, nullptr, d_out, nullptr, bo,
                                      MROWS, DMODEL, DATTN);
}